// round 4
// baseline (speedup 1.0000x reference)
#include <cuda_runtime.h>
#include <cuda_fp16.h>
#include <mma.h>
#include <cstddef>

using namespace nvcuda;

// Problem constants (from reference): N=100000, E=1600000, CIN=128, COUT=64, S=9.
#define MAXN 100000
#define NCOLS 640           // 9 slots * 64 + 64 root cols
#define SLOTC 576           // 9 * 64 slot columns

// ---------------- scratch (static __device__ globals; no runtime alloc) ----------
__device__ __half g_B1h[128 * NCOLS];             // fp16 repacked [K=128, 640] W1|root1
__device__ __half g_B2h[64 * NCOLS];              // fp16 repacked [K=64, 640]  W2|root2
__device__ __half g_Ah[(size_t)MAXN * 128];       // fp16 copy of x (layer-1 A operand)
__device__ __half g_xWh[(size_t)MAXN * SLOTC];    // fp16 slot table (115 MB, ~L2-resident)
__device__ float  g_rootp[(size_t)MAXN * 64];     // fp32 root-term per node
__device__ float  g_agg[(size_t)MAXN * 64];       // fp32 edge aggregation target
__device__ __half g_hh[(size_t)MAXN * 128];       // layer-2 A: [relu1 | skip] fp16
__device__ __half g_h2h[(size_t)MAXN * 64];       // layer-3 A fp16

// ---------------- repack W[S,K,64] + root[K,64] -> Bh[K,640] fp16 ------------------
__global__ void repack_kernel(const float* __restrict__ W, const float* __restrict__ root,
                              __half* __restrict__ B, int K) {
    int i = blockIdx.x * blockDim.x + threadIdx.x;
    int total = K * NCOLS;
    if (i >= total) return;
    int k = i / NCOLS, c = i - k * NCOLS;
    float v;
    if (c < SLOTC) {
        int s = c >> 6, o = c & 63;
        v = W[((size_t)s * K + k) * 64 + o];
    } else {
        v = root[(size_t)k * 64 + (c - SLOTC)];
    }
    B[i] = __float2half_rn(v);
}

// ---------------- fp32 -> fp16 convert (for x) ------------------------------------
__global__ void f2h_kernel(const float* __restrict__ src, __half* __restrict__ dst, int n4) {
    int i = blockIdx.x * blockDim.x + threadIdx.x;
    if (i >= n4) return;
    float4 v = __ldg(reinterpret_cast<const float4*>(src) + i);
    __half2 h0 = __floats2half2_rn(v.x, v.y);
    __half2 h1 = __floats2half2_rn(v.z, v.w);
    uint2 packed;
    packed.x = *reinterpret_cast<unsigned*>(&h0);
    packed.y = *reinterpret_cast<unsigned*>(&h1);
    reinterpret_cast<uint2*>(dst)[i] = packed;
}

// ---------------- WMMA GEMM: C[M,640] = Ah[M,K] * Bh[K,640], fp32 accum -----------
// BM=BN=64, BK=16. 256 threads = 8 warps as 4x2; each warp: 16x32 (2 wmma tiles).
// Epilogue: col tiles 0..8 -> fp16 slot table; tile 9 -> fp32 root term.
__global__ void wmma_gemm_kernel(const __half* __restrict__ Ah, const __half* __restrict__ Bh,
                                 __half* __restrict__ Ch, float* __restrict__ Cr,
                                 int M, int K) {
    __shared__ union {
        struct { __half A[64 * 24]; __half B[16 * 72]; } ld;
        float C[64 * 72];
    } sm;

    int tid = threadIdx.x;
    int wid = tid >> 5;
    int wm = wid >> 1;          // 0..3: warp row (16 rows each)
    int wn = wid & 1;           // 0..1: warp col (32 cols each)
    int row0 = blockIdx.y * 64;
    int col0 = blockIdx.x * 64;

    wmma::fragment<wmma::accumulator, 16, 16, 16, float> acc[2];
    wmma::fill_fragment(acc[0], 0.0f);
    wmma::fill_fragment(acc[1], 0.0f);

    int ar = tid >> 2, ac = (tid & 3) << 2;     // A tile coords: 64 rows x 16 cols
    int br = tid >> 4, bc = (tid & 15) << 2;    // B tile coords: 16 rows x 64 cols

    for (int kb = 0; kb < K; kb += 16) {
        uint2 av = make_uint2(0u, 0u);
        int gr = row0 + ar;
        if (gr < M) av = *reinterpret_cast<const uint2*>(Ah + (size_t)gr * K + kb + ac);
        *reinterpret_cast<uint2*>(&sm.ld.A[ar * 24 + ac]) = av;
        uint2 bv = *reinterpret_cast<const uint2*>(Bh + (size_t)(kb + br) * NCOLS + col0 + bc);
        *reinterpret_cast<uint2*>(&sm.ld.B[br * 72 + bc]) = bv;
        __syncthreads();

        wmma::fragment<wmma::matrix_a, 16, 16, 16, __half, wmma::row_major> a;
        wmma::load_matrix_sync(a, &sm.ld.A[wm * 16 * 24], 24);
        #pragma unroll
        for (int j = 0; j < 2; j++) {
            wmma::fragment<wmma::matrix_b, 16, 16, 16, __half, wmma::row_major> b;
            wmma::load_matrix_sync(b, &sm.ld.B[wn * 32 + j * 16], 72);
            wmma::mma_sync(acc[j], a, b, acc[j]);
        }
        __syncthreads();
    }

    // stage accumulators through smem (float), then typed writeback
    #pragma unroll
    for (int j = 0; j < 2; j++)
        wmma::store_matrix_sync(&sm.C[(wm * 16) * 72 + wn * 32 + j * 16], acc[j], 72,
                                wmma::mem_row_major);
    __syncthreads();

    int r = tid >> 2, c0 = (tid & 3) << 4;      // each thread: 16 consecutive cols of a row
    int gr = row0 + r;
    if (gr < M) {
        if (col0 < SLOTC) {
            __half2 tmp[8];
            #pragma unroll
            for (int i = 0; i < 8; i++)
                tmp[i] = __floats2half2_rn(sm.C[r * 72 + c0 + 2 * i],
                                           sm.C[r * 72 + c0 + 2 * i + 1]);
            uint4* dst = reinterpret_cast<uint4*>(Ch + (size_t)gr * SLOTC + col0 + c0);
            dst[0] = reinterpret_cast<uint4*>(tmp)[0];
            dst[1] = reinterpret_cast<uint4*>(tmp)[1];
        } else {
            float4* dst = reinterpret_cast<float4*>(Cr + (size_t)gr * 64 + c0);
            #pragma unroll
            for (int i = 0; i < 4; i++)
                dst[i] = *reinterpret_cast<float4*>(&sm.C[r * 72 + c0 + 4 * i]);
        }
    }
}

// ---------------- edge kernel: 16 threads per edge --------------------------------
// Each thread owns 4 consecutive output channels. Gather fp16 (8B/slot/thread),
// accumulate fp32, scatter one red.global.add.v4.f32 per thread.
__global__ void edge_kernel(const __half* __restrict__ xWh, const int* __restrict__ ei,
                            const float* __restrict__ attr, float* __restrict__ agg, int E) {
    int gtid = blockIdx.x * blockDim.x + threadIdx.x;
    int e    = gtid >> 4;        // edge id
    int t    = gtid & 15;        // 0..15: which 4-channel group
    if (e >= E) return;

    int s = __ldg(&ei[e]);           // source (row 0)
    int d = __ldg(&ei[E + e]);       // target (row 1)
    float2 uv = __ldg(reinterpret_cast<const float2*>(attr) + e);
    float u0 = uv.x, u1 = uv.y;

    float b0[3], b1[3];
    b0[0] = 0.5f * (1.0f - u0) * (1.0f - u0);
    b0[1] = -u0 * u0 + u0 + 0.5f;
    b0[2] = 0.5f * u0 * u0;
    b1[0] = 0.5f * (1.0f - u1) * (1.0f - u1);
    b1[1] = -u1 * u1 + u1 + 0.5f;
    b1[2] = 0.5f * u1 * u1;

    const __half* base = xWh + (size_t)s * SLOTC + 4 * t;
    float4 acc = {0.0f, 0.0f, 0.0f, 0.0f};
    #pragma unroll
    for (int k1 = 0; k1 < 3; k1++) {
        float4 part = {0.0f, 0.0f, 0.0f, 0.0f};
        #pragma unroll
        for (int k0 = 0; k0 < 3; k0++) {
            float w = b0[k0];
            uint2 raw = __ldg(reinterpret_cast<const uint2*>(base + (k0 + 3 * k1) * 64));
            float2 va = __half22float2(*reinterpret_cast<const __half2*>(&raw.x));
            float2 vb = __half22float2(*reinterpret_cast<const __half2*>(&raw.y));
            part.x += w * va.x; part.y += w * va.y;
            part.z += w * vb.x; part.w += w * vb.y;
        }
        float w1 = b1[k1];
        acc.x += w1 * part.x; acc.y += w1 * part.y;
        acc.z += w1 * part.z; acc.w += w1 * part.w;
    }
    float* outp = agg + (size_t)d * 64 + 4 * t;
    asm volatile("red.global.add.v4.f32 [%0], {%1, %2, %3, %4};"
                 :: "l"(outp), "f"(acc.x), "f"(acc.y), "f"(acc.z), "f"(acc.w)
                 : "memory");
}

// ---------------- finalize (layers 1,2): relu -> fp16 A operand, optional skip ----
__global__ void finalize_h_kernel(const float* __restrict__ agg, const float* __restrict__ rootp,
                                  const float* __restrict__ bias, const float* __restrict__ skip,
                                  __half* __restrict__ hout, int N, int ostride) {
    int i = blockIdx.x * blockDim.x + threadIdx.x;   // one thread per 2 channels
    if (i >= N * 32) return;
    int n = i >> 5, o = (i & 31) * 2;
    int base = n * 64 + o;
    float v0 = fmaxf(agg[base]     + rootp[base]     + bias[o],     0.0f);
    float v1 = fmaxf(agg[base + 1] + rootp[base + 1] + bias[o + 1], 0.0f);
    __half2* dst = reinterpret_cast<__half2*>(hout + (size_t)n * ostride + o);
    *dst = __floats2half2_rn(v0, v1);
    if (skip) {
        __half2* dsk = reinterpret_cast<__half2*>(hout + (size_t)n * ostride + 64 + o);
        *dsk = __floats2half2_rn(skip[base], skip[base + 1]);
    }
}

// ---------------- finalize (layer 3): relu -> fp32 final output --------------------
__global__ void finalize_f_kernel(const float* __restrict__ agg, const float* __restrict__ rootp,
                                  const float* __restrict__ bias, float* __restrict__ out, int N) {
    int i = blockIdx.x * blockDim.x + threadIdx.x;
    if (i >= N * 64) return;
    int o = i & 63;
    out[i] = fmaxf(agg[i] + rootp[i] + bias[o], 0.0f);
}

// ---------------- launch ----------------------------------------------------------
extern "C" void kernel_launch(void* const* d_in, const int* in_sizes, int n_in,
                              void* d_out, int out_size) {
    const float* x     = (const float*)d_in[0];
    const float* skip  = (const float*)d_in[1];
    const int*   ei    = (const int*)  d_in[2];
    const float* attr  = (const float*)d_in[3];
    const float* W1    = (const float*)d_in[4];
    const float* root1 = (const float*)d_in[5];
    const float* b1    = (const float*)d_in[6];
    const float* W2    = (const float*)d_in[7];
    const float* root2 = (const float*)d_in[8];
    const float* b2    = (const float*)d_in[9];
    float* out = (float*)d_out;

    int N = in_sizes[0] / 128;
    int E = in_sizes[2] / 2;

    __half *B1h, *B2h, *Ah, *xWh, *hh, *h2h;
    float *rootp, *agg;
    cudaGetSymbolAddress((void**)&B1h,   g_B1h);
    cudaGetSymbolAddress((void**)&B2h,   g_B2h);
    cudaGetSymbolAddress((void**)&Ah,    g_Ah);
    cudaGetSymbolAddress((void**)&xWh,   g_xWh);
    cudaGetSymbolAddress((void**)&rootp, g_rootp);
    cudaGetSymbolAddress((void**)&agg,   g_agg);
    cudaGetSymbolAddress((void**)&hh,    g_hh);
    cudaGetSymbolAddress((void**)&h2h,   g_h2h);

    repack_kernel<<<(128 * NCOLS + 255) / 256, 256>>>(W1, root1, B1h, 128);
    repack_kernel<<<(64 * NCOLS + 255) / 256, 256>>>(W2, root2, B2h, 64);
    f2h_kernel<<<(N * 32 + 255) / 256, 256>>>(x, Ah, N * 32);   // N*128/4 float4s

    dim3 ggrid(NCOLS / 64, (N + 63) / 64);
    int eblocks  = (E * 16 + 255) / 256;          // 16 threads per edge
    int f2blocks = (N * 32 + 255) / 256;          // finalize_h: thread per 2 channels
    int fblocks  = (N * 64 + 255) / 256;
    size_t aggBytes = (size_t)N * 64 * sizeof(float);

    // ---- layer 1: conv1(x) ----
    wmma_gemm_kernel<<<ggrid, 256>>>(Ah, B1h, xWh, rootp, N, 128);
    cudaMemsetAsync(agg, 0, aggBytes);
    edge_kernel<<<eblocks, 256>>>(xWh, ei, attr, agg, E);
    finalize_h_kernel<<<f2blocks, 256>>>(agg, rootp, b1, skip, hh, N, 128); // [relu|skip]

    // ---- layer 2: conv1(h) (shared weights) ----
    wmma_gemm_kernel<<<ggrid, 256>>>(hh, B1h, xWh, rootp, N, 128);
    cudaMemsetAsync(agg, 0, aggBytes);
    edge_kernel<<<eblocks, 256>>>(xWh, ei, attr, agg, E);
    finalize_h_kernel<<<f2blocks, 256>>>(agg, rootp, b1, nullptr, h2h, N, 64);

    // ---- layer 3: conv2(h2) ----
    wmma_gemm_kernel<<<ggrid, 256>>>(h2h, B2h, xWh, rootp, N, 64);
    cudaMemsetAsync(agg, 0, aggBytes);
    edge_kernel<<<eblocks, 256>>>(xWh, ei, attr, agg, E);
    finalize_f_kernel<<<fblocks, 256>>>(agg, rootp, b2, out, N);
}

// round 9
// speedup vs baseline: 1.0705x; 1.0705x over previous
#include <cuda_runtime.h>
#include <cuda_fp16.h>
#include <mma.h>
#include <cstddef>

using namespace nvcuda;

// Problem constants: N=100000, E=1600000, CIN=128, COUT=64, S=9.
#define MAXN 100000
#define MAXE 1600000
#define NCOLS 640           // 9 slots * 64 + 64 root cols
#define SLOTC 576           // 9 * 64 slot columns

// ---------------- scratch (static __device__ globals; no runtime alloc) ----------
__device__ __half g_B1h[128 * NCOLS];
__device__ __half g_B2h[64 * NCOLS];
__device__ __half g_Ah[(size_t)MAXN * 128];
__device__ __half g_xWh[(size_t)MAXN * SLOTC];    // fp16 slot table (115 MB)
__device__ float  g_rootp[(size_t)MAXN * 64];
__device__ float  g_agg[(size_t)MAXN * 64];
__device__ __half g_hh[(size_t)MAXN * 128];
__device__ __half g_h2h[(size_t)MAXN * 64];
// sort scratch
__device__ int    g_cnt[MAXN];                    // per-src degree
__device__ int    g_off[MAXN];                    // per-block exclusive scan
__device__ int    g_blk[512];                     // block sums
__device__ int    g_cur[MAXN];                    // scatter cursors
__device__ int    g_srcS[MAXE];
__device__ int    g_dstS[MAXE];
__device__ float2 g_attrS[MAXE];

// ---------------- repack W[S,K,64] + root[K,64] -> Bh[K,640] fp16 ------------------
__global__ void repack_kernel(const float* __restrict__ W, const float* __restrict__ root,
                              __half* __restrict__ B, int K) {
    int i = blockIdx.x * blockDim.x + threadIdx.x;
    if (i >= K * NCOLS) return;
    int k = i / NCOLS, c = i - k * NCOLS;
    float v = (c < SLOTC) ? W[(((size_t)(c >> 6)) * K + k) * 64 + (c & 63)]
                          : root[(size_t)k * 64 + (c - SLOTC)];
    B[i] = __float2half_rn(v);
}

// ---------------- fp32 -> fp16 convert (for x) ------------------------------------
__global__ void f2h_kernel(const float* __restrict__ src, __half* __restrict__ dst, int n4) {
    int i = blockIdx.x * blockDim.x + threadIdx.x;
    if (i >= n4) return;
    float4 v = __ldg(reinterpret_cast<const float4*>(src) + i);
    __half2 h0 = __floats2half2_rn(v.x, v.y);
    __half2 h1 = __floats2half2_rn(v.z, v.w);
    uint2 p; p.x = *reinterpret_cast<unsigned*>(&h0); p.y = *reinterpret_cast<unsigned*>(&h1);
    reinterpret_cast<uint2*>(dst)[i] = p;
}

// ================= counting sort of edges by src ===================================
__global__ void hist_kernel(const int* __restrict__ ei, int E) {
    int i = blockIdx.x * blockDim.x + threadIdx.x;
    if (i < E) atomicAdd(&g_cnt[ei[i]], 1);
}
// block-level exclusive scan (256 wide)
__global__ void scan1_kernel(int N) {
    __shared__ int sm[256];
    int i = blockIdx.x * 256 + threadIdx.x;
    int v = (i < N) ? g_cnt[i] : 0;
    sm[threadIdx.x] = v;
    __syncthreads();
    int acc = v;
    #pragma unroll
    for (int d = 1; d < 256; d <<= 1) {
        int t = (threadIdx.x >= d) ? sm[threadIdx.x - d] : 0;
        __syncthreads();
        acc += t; sm[threadIdx.x] = acc;
        __syncthreads();
    }
    if (i < N) g_off[i] = acc - v;                 // exclusive within block
    if (threadIdx.x == 255) g_blk[blockIdx.x] = acc;   // block total
}
__global__ void scan2_kernel(int nb) {
    __shared__ int sm[512];
    int t = threadIdx.x;
    int v = (t < nb) ? g_blk[t] : 0;
    sm[t] = v;
    __syncthreads();
    int acc = v;
    #pragma unroll
    for (int d = 1; d < 512; d <<= 1) {
        int x = (t >= d) ? sm[t - d] : 0;
        __syncthreads();
        acc += x; sm[t] = acc;
        __syncthreads();
    }
    g_blk[t] = acc - v;                            // exclusive block offsets
}
__global__ void scan3_kernel(int N) {
    int i = blockIdx.x * 256 + threadIdx.x;
    if (i < N) g_cur[i] = g_off[i] + g_blk[blockIdx.x];
}
__global__ void scatter_kernel(const int* __restrict__ ei, const float* __restrict__ attr, int E) {
    int e = blockIdx.x * blockDim.x + threadIdx.x;
    if (e >= E) return;
    int s = ei[e];
    int pos = atomicAdd(&g_cur[s], 1);
    g_srcS[pos] = s;
    g_dstS[pos] = ei[E + e];
    g_attrS[pos] = reinterpret_cast<const float2*>(attr)[e];
}

// ---------------- WMMA GEMM: C[M,640] = Ah[M,K] * Bh[K,640], fp32 accum -----------
// BM=128, BN=64, BK=32. 256 threads = 8 warps (4x2); warp tile 32x32 (4 fragments).
__global__ void wmma_gemm_kernel(const __half* __restrict__ Ah, const __half* __restrict__ Bh,
                                 __half* __restrict__ Ch, float* __restrict__ Cr,
                                 int M, int K) {
    __shared__ union {
        struct { __half A[128 * 40]; __half B[32 * 72]; } ld;
        float C[128 * 72];
    } sm;

    int tid = threadIdx.x;
    int wid = tid >> 5;
    int wm = wid >> 1;          // 0..3: warp row (32 rows each)
    int wn = wid & 1;           // 0..1: warp col (32 cols each)
    int row0 = blockIdx.y * 128;
    int col0 = blockIdx.x * 64;

    wmma::fragment<wmma::accumulator, 16, 16, 16, float> acc[2][2];
    #pragma unroll
    for (int i = 0; i < 2; i++)
        #pragma unroll
        for (int j = 0; j < 2; j++)
            wmma::fill_fragment(acc[i][j], 0.0f);

    int ar = tid >> 1, ac = (tid & 1) << 4;     // A: 128 rows x 32 cols, 16 halves/thread
    int br = tid >> 3, bc = (tid & 7) << 3;     // B: 32 rows x 64 cols, 8 halves/thread

    for (int kb = 0; kb < K; kb += 32) {
        int gr = row0 + ar;
        uint4 av0 = make_uint4(0u,0u,0u,0u), av1 = av0;
        if (gr < M) {
            const uint4* ap = reinterpret_cast<const uint4*>(Ah + (size_t)gr * K + kb + ac);
            av0 = ap[0]; av1 = ap[1];
        }
        uint4* asp = reinterpret_cast<uint4*>(&sm.ld.A[ar * 40 + ac]);
        asp[0] = av0; asp[1] = av1;
        uint4 bv = *reinterpret_cast<const uint4*>(Bh + (size_t)(kb + br) * NCOLS + col0 + bc);
        *reinterpret_cast<uint4*>(&sm.ld.B[br * 72 + bc]) = bv;
        __syncthreads();

        #pragma unroll
        for (int ks = 0; ks < 32; ks += 16) {
            wmma::fragment<wmma::matrix_a, 16, 16, 16, __half, wmma::row_major> a[2];
            wmma::fragment<wmma::matrix_b, 16, 16, 16, __half, wmma::row_major> b[2];
            #pragma unroll
            for (int i = 0; i < 2; i++)
                wmma::load_matrix_sync(a[i], &sm.ld.A[(wm * 32 + i * 16) * 40 + ks], 40);
            #pragma unroll
            for (int j = 0; j < 2; j++)
                wmma::load_matrix_sync(b[j], &sm.ld.B[ks * 72 + wn * 32 + j * 16], 72);
            #pragma unroll
            for (int i = 0; i < 2; i++)
                #pragma unroll
                for (int j = 0; j < 2; j++)
                    wmma::mma_sync(acc[i][j], a[i], b[j], acc[i][j]);
        }
        __syncthreads();
    }

    #pragma unroll
    for (int i = 0; i < 2; i++)
        #pragma unroll
        for (int j = 0; j < 2; j++)
            wmma::store_matrix_sync(&sm.C[(wm * 32 + i * 16) * 72 + wn * 32 + j * 16],
                                    acc[i][j], 72, wmma::mem_row_major);
    __syncthreads();

    int r = tid >> 1, c0 = (tid & 1) * 32;      // each thread: 32 cols of one row
    int gr = row0 + r;
    if (gr < M) {
        if (col0 < SLOTC) {
            __half2 tmp[16];
            #pragma unroll
            for (int i = 0; i < 16; i++)
                tmp[i] = __floats2half2_rn(sm.C[r * 72 + c0 + 2 * i],
                                           sm.C[r * 72 + c0 + 2 * i + 1]);
            uint4* dst = reinterpret_cast<uint4*>(Ch + (size_t)gr * SLOTC + col0 + c0);
            #pragma unroll
            for (int i = 0; i < 4; i++) dst[i] = reinterpret_cast<uint4*>(tmp)[i];
        } else {
            float4* dst = reinterpret_cast<float4*>(Cr + (size_t)gr * 64 + c0);
            #pragma unroll
            for (int i = 0; i < 8; i++)
                dst[i] = *reinterpret_cast<float4*>(&sm.C[r * 72 + c0 + 4 * i]);
        }
    }
}

// ---------------- edge kernel: 16 threads per edge, src-sorted order --------------
__global__ void edge_kernel(const __half* __restrict__ xWh, const int* __restrict__ srcS,
                            const int* __restrict__ dstS, const float2* __restrict__ attrS,
                            float* __restrict__ agg, int E) {
    int gtid = blockIdx.x * blockDim.x + threadIdx.x;
    int e    = gtid >> 4;
    int t    = gtid & 15;
    if (e >= E) return;

    int s = __ldg(&srcS[e]);
    int d = __ldg(&dstS[e]);
    float2 uv = __ldg(&attrS[e]);
    float u0 = uv.x, u1 = uv.y;

    float b0[3], b1[3];
    b0[0] = 0.5f * (1.0f - u0) * (1.0f - u0);
    b0[1] = -u0 * u0 + u0 + 0.5f;
    b0[2] = 0.5f * u0 * u0;
    b1[0] = 0.5f * (1.0f - u1) * (1.0f - u1);
    b1[1] = -u1 * u1 + u1 + 0.5f;
    b1[2] = 0.5f * u1 * u1;

    const __half* base = xWh + (size_t)s * SLOTC + 4 * t;
    float4 acc = {0.0f, 0.0f, 0.0f, 0.0f};
    #pragma unroll
    for (int k1 = 0; k1 < 3; k1++) {
        float4 part = {0.0f, 0.0f, 0.0f, 0.0f};
        #pragma unroll
        for (int k0 = 0; k0 < 3; k0++) {
            float w = b0[k0];
            uint2 raw = __ldg(reinterpret_cast<const uint2*>(base + (k0 + 3 * k1) * 64));
            float2 va = __half22float2(*reinterpret_cast<const __half2*>(&raw.x));
            float2 vb = __half22float2(*reinterpret_cast<const __half2*>(&raw.y));
            part.x += w * va.x; part.y += w * va.y;
            part.z += w * vb.x; part.w += w * vb.y;
        }
        float w1 = b1[k1];
        acc.x += w1 * part.x; acc.y += w1 * part.y;
        acc.z += w1 * part.z; acc.w += w1 * part.w;
    }
    float* outp = agg + (size_t)d * 64 + 4 * t;
    asm volatile("red.global.add.v4.f32 [%0], {%1, %2, %3, %4};"
                 :: "l"(outp), "f"(acc.x), "f"(acc.y), "f"(acc.z), "f"(acc.w)
                 : "memory");
}

// ---------------- finalize (layers 1,2): relu -> fp16 A operand, optional skip ----
__global__ void finalize_h_kernel(const float* __restrict__ agg, const float* __restrict__ rootp,
                                  const float* __restrict__ bias, const float* __restrict__ skip,
                                  __half* __restrict__ hout, int N, int ostride) {
    int i = blockIdx.x * blockDim.x + threadIdx.x;
    if (i >= N * 32) return;
    int n = i >> 5, o = (i & 31) * 2;
    int base = n * 64 + o;
    float v0 = fmaxf(agg[base]     + rootp[base]     + bias[o],     0.0f);
    float v1 = fmaxf(agg[base + 1] + rootp[base + 1] + bias[o + 1], 0.0f);
    *reinterpret_cast<__half2*>(hout + (size_t)n * ostride + o) = __floats2half2_rn(v0, v1);
    if (skip)
        *reinterpret_cast<__half2*>(hout + (size_t)n * ostride + 64 + o) =
            __floats2half2_rn(skip[base], skip[base + 1]);
}

__global__ void finalize_f_kernel(const float* __restrict__ agg, const float* __restrict__ rootp,
                                  const float* __restrict__ bias, float* __restrict__ out, int N) {
    int i = blockIdx.x * blockDim.x + threadIdx.x;
    if (i >= N * 64) return;
    out[i] = fmaxf(agg[i] + rootp[i] + bias[i & 63], 0.0f);
}

// ---------------- launch ----------------------------------------------------------
extern "C" void kernel_launch(void* const* d_in, const int* in_sizes, int n_in,
                              void* d_out, int out_size) {
    const float* x     = (const float*)d_in[0];
    const float* skip  = (const float*)d_in[1];
    const int*   ei    = (const int*)  d_in[2];
    const float* attr  = (const float*)d_in[3];
    const float* W1    = (const float*)d_in[4];
    const float* root1 = (const float*)d_in[5];
    const float* b1    = (const float*)d_in[6];
    const float* W2    = (const float*)d_in[7];
    const float* root2 = (const float*)d_in[8];
    const float* b2    = (const float*)d_in[9];
    float* out = (float*)d_out;

    int N = in_sizes[0] / 128;
    int E = in_sizes[2] / 2;

    __half *B1h, *B2h, *Ah, *xWh, *hh, *h2h;
    float *rootp, *agg;
    int *cnt, *srcS, *dstS;
    float2 *attrS;
    cudaGetSymbolAddress((void**)&B1h,   g_B1h);
    cudaGetSymbolAddress((void**)&B2h,   g_B2h);
    cudaGetSymbolAddress((void**)&Ah,    g_Ah);
    cudaGetSymbolAddress((void**)&xWh,   g_xWh);
    cudaGetSymbolAddress((void**)&rootp, g_rootp);
    cudaGetSymbolAddress((void**)&agg,   g_agg);
    cudaGetSymbolAddress((void**)&hh,    g_hh);
    cudaGetSymbolAddress((void**)&h2h,   g_h2h);
    cudaGetSymbolAddress((void**)&cnt,   g_cnt);
    cudaGetSymbolAddress((void**)&srcS,  g_srcS);
    cudaGetSymbolAddress((void**)&dstS,  g_dstS);
    cudaGetSymbolAddress((void**)&attrS, g_attrS);

    repack_kernel<<<(128 * NCOLS + 255) / 256, 256>>>(W1, root1, B1h, 128);
    repack_kernel<<<(64 * NCOLS + 255) / 256, 256>>>(W2, root2, B2h, 64);
    f2h_kernel<<<(N * 32 + 255) / 256, 256>>>(x, Ah, N * 32);

    // ---- counting sort of edges by src (reused by all 3 layers) ----
    int nb = (N + 255) / 256;
    cudaMemsetAsync(cnt, 0, (size_t)N * sizeof(int));
    hist_kernel<<<(E + 255) / 256, 256>>>(ei, E);
    scan1_kernel<<<nb, 256>>>(N);
    scan2_kernel<<<1, 512>>>(nb);
    scan3_kernel<<<nb, 256>>>(N);
    scatter_kernel<<<(E + 255) / 256, 256>>>(ei, attr, E);

    dim3 ggrid(NCOLS / 64, (N + 127) / 128);
    int eblocks  = (E * 16 + 255) / 256;
    int f2blocks = (N * 32 + 255) / 256;
    int fblocks  = (N * 64 + 255) / 256;
    size_t aggBytes = (size_t)N * 64 * sizeof(float);

    // ---- layer 1: conv1(x) ----
    wmma_gemm_kernel<<<ggrid, 256>>>(Ah, B1h, xWh, rootp, N, 128);
    cudaMemsetAsync(agg, 0, aggBytes);
    edge_kernel<<<eblocks, 256>>>(xWh, srcS, dstS, attrS, agg, E);
    finalize_h_kernel<<<f2blocks, 256>>>(agg, rootp, b1, skip, hh, N, 128);

    // ---- layer 2: conv1(h) (shared weights) ----
    wmma_gemm_kernel<<<ggrid, 256>>>(hh, B1h, xWh, rootp, N, 128);
    cudaMemsetAsync(agg, 0, aggBytes);
    edge_kernel<<<eblocks, 256>>>(xWh, srcS, dstS, attrS, agg, E);
    finalize_h_kernel<<<f2blocks, 256>>>(agg, rootp, b1, nullptr, h2h, N, 64);

    // ---- layer 3: conv2(h2) ----
    wmma_gemm_kernel<<<ggrid, 256>>>(h2h, B2h, xWh, rootp, N, 64);
    cudaMemsetAsync(agg, 0, aggBytes);
    edge_kernel<<<eblocks, 256>>>(xWh, srcS, dstS, attrS, agg, E);
    finalize_f_kernel<<<fblocks, 256>>>(agg, rootp, b2, out, N);
}